// round 2
// baseline (speedup 1.0000x reference)
#include <cuda_runtime.h>
#include <cstdint>

#define BATCH        32768
#define FEAT_DIM     512
#define NUM_CLASSES  1000
#define KC           2
#define WARPS_PER_BLOCK 8
#define THREADS   (WARPS_PER_BLOCK * 32)

// Scratch via __device__ globals (allocation-free).
__device__ double g_acc;
__device__ int    g_is64;

// Detect label dtype (int32 vs int64) + zero the accumulator.
// Safe: labels buffer is >= 32768*4 bytes in either case; we read 4 KB.
__global__ void mcl_prep(const int* __restrict__ labels_words) {
    int ornz = 0;
    for (int i = 1; i < 1024; i += 2) ornz |= labels_words[i];
    g_is64 = (ornz == 0) ? 1 : 0;   // int64: odd words are zero high-halves
    g_acc = 0.0;
}

__global__ __launch_bounds__(THREADS) void mcl_main(
    const float* __restrict__ x,
    const void*  __restrict__ labels,
    const float* __restrict__ centers)
{
    const int warp_global = (blockIdx.x * THREADS + threadIdx.x) >> 5;
    const int lane = threadIdx.x & 31;
    const int warp_local = threadIdx.x >> 5;

    float d0 = 0.0f, d1 = 0.0f;

    if (warp_global < BATCH) {
        long long lbl;
        if (g_is64)
            lbl = ((const long long*)labels)[warp_global];
        else
            lbl = (long long)((const int*)labels)[warp_global];
        // Defensive clamp: misdetection -> wrong answer (diagnosable), not a crash.
        if (lbl < 0 || lbl >= NUM_CLASSES) lbl = 0;

        const float4* __restrict__ xr = reinterpret_cast<const float4*>(
            x + (size_t)warp_global * FEAT_DIM);
        const float4* __restrict__ c0 = reinterpret_cast<const float4*>(
            centers + (size_t)lbl * (KC * FEAT_DIM));
        const float4* __restrict__ c1 = c0 + (FEAT_DIM / 4);

        #pragma unroll
        for (int i = 0; i < FEAT_DIM / 4 / 32; i++) {   // 4 iterations
            const int idx = lane + 32 * i;
            const float4 xv = xr[idx];
            const float4 a  = c0[idx];
            const float4 b  = c1[idx];
            float t;
            t = xv.x - a.x; d0 = fmaf(t, t, d0);
            t = xv.y - a.y; d0 = fmaf(t, t, d0);
            t = xv.z - a.z; d0 = fmaf(t, t, d0);
            t = xv.w - a.w; d0 = fmaf(t, t, d0);
            t = xv.x - b.x; d1 = fmaf(t, t, d1);
            t = xv.y - b.y; d1 = fmaf(t, t, d1);
            t = xv.z - b.z; d1 = fmaf(t, t, d1);
            t = xv.w - b.w; d1 = fmaf(t, t, d1);
        }
    }

    // Warp tree-reduce both sums, then min over the K=2 centers.
    #pragma unroll
    for (int off = 16; off > 0; off >>= 1) {
        d0 += __shfl_xor_sync(0xffffffffu, d0, off);
        d1 += __shfl_xor_sync(0xffffffffu, d1, off);
    }
    float md = fminf(d0, d1);

    __shared__ float s_part[WARPS_PER_BLOCK];
    if (lane == 0) s_part[warp_local] = (warp_global < BATCH) ? md : 0.0f;
    __syncthreads();

    if (threadIdx.x == 0) {
        float block_sum = 0.0f;
        #pragma unroll
        for (int i = 0; i < WARPS_PER_BLOCK; i++) block_sum += s_part[i];
        atomicAdd(&g_acc, (double)block_sum);
    }
}

__global__ void mcl_finalize(float* __restrict__ out) {
    out[0] = (float)(g_acc / (double)BATCH);
}

extern "C" void kernel_launch(void* const* d_in, const int* in_sizes, int n_in,
                              void* d_out, int out_size)
{
    // Identify inputs by element count (robust to ordering):
    //   x: 32768*512 = 16777216, centers: 2000*512 = 1024000, labels: 32768.
    const float* x       = nullptr;
    const void*  labels  = nullptr;
    const float* centers = nullptr;
    for (int i = 0; i < n_in; i++) {
        if (in_sizes[i] == BATCH * FEAT_DIM)                x = (const float*)d_in[i];
        else if (in_sizes[i] == NUM_CLASSES * KC * FEAT_DIM) centers = (const float*)d_in[i];
        else if (in_sizes[i] == BATCH)                       labels = d_in[i];
    }
    float* out = (float*)d_out;

    mcl_prep<<<1, 1>>>((const int*)labels);

    const int blocks = (BATCH + WARPS_PER_BLOCK - 1) / WARPS_PER_BLOCK;
    mcl_main<<<blocks, THREADS>>>(x, labels, centers);

    mcl_finalize<<<1, 1>>>(out);
}

// round 3
// speedup vs baseline: 1.0737x; 1.0737x over previous
#include <cuda_runtime.h>
#include <cstdint>

#define BATCH        32768
#define FEAT_DIM     512
#define NUM_CLASSES  1000
#define KC           2
#define WARPS_PER_BLOCK 8
#define THREADS   (WARPS_PER_BLOCK * 32)

// Scratch via __device__ globals (allocation-free).
__device__ double        g_acc;
__device__ int           g_is64;
__device__ unsigned int  g_count;

// Detect label dtype (int32 vs int64) + zero accumulators.
// 512 threads read the 512 odd 32-bit words of the first 4 KB (in-bounds for
// either dtype: buffer is >= 128 KB). int64 little-endian small labels have
// all-zero high words; int32 random labels in [0,1000) cannot.
__global__ __launch_bounds__(512) void mcl_prep(const int* __restrict__ labels_words) {
    const int v = labels_words[2 * threadIdx.x + 1];
    const int any_nz = __syncthreads_or(v != 0);
    if (threadIdx.x == 0) {
        g_is64 = any_nz ? 0 : 1;
        g_acc = 0.0;
        g_count = 0u;
    }
}

__global__ __launch_bounds__(THREADS) void mcl_main(
    const float* __restrict__ x,
    const void*  __restrict__ labels,
    const float* __restrict__ centers,
    float*       __restrict__ out)
{
    const int warp_global = (blockIdx.x * THREADS + threadIdx.x) >> 5;
    const int lane = threadIdx.x & 31;
    const int warp_local = threadIdx.x >> 5;

    float d0 = 0.0f, d1 = 0.0f;

    if (warp_global < BATCH) {
        long long lbl;
        if (g_is64)
            lbl = ((const long long*)labels)[warp_global];
        else
            lbl = (long long)((const int*)labels)[warp_global];
        // Defensive clamp: misdetection -> wrong answer (diagnosable), not a crash.
        if (lbl < 0 || lbl >= NUM_CLASSES) lbl = 0;

        const float4* __restrict__ xr = reinterpret_cast<const float4*>(
            x + (size_t)warp_global * FEAT_DIM);
        const float4* __restrict__ c0 = reinterpret_cast<const float4*>(
            centers + (size_t)lbl * (KC * FEAT_DIM));
        const float4* __restrict__ c1 = c0 + (FEAT_DIM / 4);

        #pragma unroll
        for (int i = 0; i < FEAT_DIM / 4 / 32; i++) {   // 4 iterations
            const int idx = lane + 32 * i;
            const float4 xv = xr[idx];
            const float4 a  = c0[idx];
            const float4 b  = c1[idx];
            float t;
            t = xv.x - a.x; d0 = fmaf(t, t, d0);
            t = xv.y - a.y; d0 = fmaf(t, t, d0);
            t = xv.z - a.z; d0 = fmaf(t, t, d0);
            t = xv.w - a.w; d0 = fmaf(t, t, d0);
            t = xv.x - b.x; d1 = fmaf(t, t, d1);
            t = xv.y - b.y; d1 = fmaf(t, t, d1);
            t = xv.z - b.z; d1 = fmaf(t, t, d1);
            t = xv.w - b.w; d1 = fmaf(t, t, d1);
        }
    }

    // Warp tree-reduce both sums, then min over the K=2 centers.
    #pragma unroll
    for (int off = 16; off > 0; off >>= 1) {
        d0 += __shfl_xor_sync(0xffffffffu, d0, off);
        d1 += __shfl_xor_sync(0xffffffffu, d1, off);
    }
    float md = fminf(d0, d1);

    __shared__ float s_part[WARPS_PER_BLOCK];
    if (lane == 0) s_part[warp_local] = (warp_global < BATCH) ? md : 0.0f;
    __syncthreads();

    if (threadIdx.x == 0) {
        float block_sum = 0.0f;
        #pragma unroll
        for (int i = 0; i < WARPS_PER_BLOCK; i++) block_sum += s_part[i];
        atomicAdd(&g_acc, (double)block_sum);
        __threadfence();
        unsigned int done = atomicAdd(&g_count, 1u);
        if (done == gridDim.x - 1) {
            // Last block: all atomics to g_acc are visible. Finalize.
            out[0] = (float)(g_acc / (double)BATCH);
        }
    }
}

extern "C" void kernel_launch(void* const* d_in, const int* in_sizes, int n_in,
                              void* d_out, int out_size)
{
    // Identify inputs by element count (robust to ordering):
    //   x: 32768*512 = 16777216, centers: 2000*512 = 1024000, labels: 32768.
    const float* x       = nullptr;
    const void*  labels  = nullptr;
    const float* centers = nullptr;
    for (int i = 0; i < n_in; i++) {
        if (in_sizes[i] == BATCH * FEAT_DIM)                 x = (const float*)d_in[i];
        else if (in_sizes[i] == NUM_CLASSES * KC * FEAT_DIM) centers = (const float*)d_in[i];
        else if (in_sizes[i] == BATCH)                       labels = d_in[i];
    }
    float* out = (float*)d_out;

    mcl_prep<<<1, 512>>>((const int*)labels);

    const int blocks = (BATCH + WARPS_PER_BLOCK - 1) / WARPS_PER_BLOCK;
    mcl_main<<<blocks, THREADS>>>(x, labels, centers, out);
}